// round 14
// baseline (speedup 1.0000x reference)
#include <cuda_runtime.h>
#include <cstdint>

#define BB 2
#define SS 2048
#define DD 1024
#define HH 16
#define NQK 2048
#define NTOT 3072

// tf32 fragment-permuted scratch (all values pre-rounded to tf32):
// g_x4 : x as A-frags        [mtg(256)][kkg(128)][lane(32)][slot(4)]
// g_w  : W as PAIRED B-frags [ntpg(192)][kkg(128)][lane(32)][4]
// g_qp : q as A-frags        [head(32)][rg(128)][kk(8)][lane(32)][slot(4)] (q pre-scaled 1/8)
// g_kp : k as PAIRED B-frags [head(32)][tile(32)][kk(8)][ntp(4)][lane(32)][4]
// g_vp : v as PAIRED B-frags [head(32)][tile(32)][kk2(8)][ntp2(4)][lane(32)][4]
__device__ float g_x4[4194304];
__device__ float g_w [3145728];
__device__ float g_qp[4194304];
__device__ float g_kp[4194304];
__device__ float g_vp[4194304];

// ---------------------------------------------------------------------------
__device__ __forceinline__ uint32_t f2tf32(float x) {
    uint32_t r; asm("cvt.rna.tf32.f32 %0, %1;" : "=r"(r) : "f"(x)); return r;
}
__device__ __forceinline__ float f2tf32f(float x) { return __uint_as_float(f2tf32(x)); }

__device__ __forceinline__ void mma_tf32(float c[4],
                                         uint32_t a0, uint32_t a1, uint32_t a2, uint32_t a3,
                                         uint32_t b0, uint32_t b1) {
    asm volatile(
        "mma.sync.aligned.m16n8k8.row.col.f32.tf32.tf32.f32 "
        "{%0,%1,%2,%3}, {%4,%5,%6,%7}, {%8,%9}, {%0,%1,%2,%3};"
        : "+f"(c[0]), "+f"(c[1]), "+f"(c[2]), "+f"(c[3])
        : "r"(a0), "r"(a1), "r"(a2), "r"(a3), "r"(b0), "r"(b1));
}

__device__ __forceinline__ void cp16(uint32_t dst, const void* src) {
    asm volatile("cp.async.cg.shared.global [%0], [%1], 16;" :: "r"(dst), "l"(src));
}
#define CP_COMMIT() asm volatile("cp.async.commit_group;" ::: "memory")

// ---------------------------------------------------------------------------
// Prepass: x -> A-frag tf32 layout.
// ---------------------------------------------------------------------------
__global__ __launch_bounds__(256) void prep_x(const float* __restrict__ x)
{
    const int g = blockIdx.x * 256 + threadIdx.x;
    const int lane = g & 31, c = g >> 5;            // chunk 0..32767
    const int kkg = c & 127, mtg = c >> 7;
    float4 o;
    float* po = (float*)&o;
#pragma unroll
    for (int sl = 0; sl < 4; sl++) {
        const int ir = (lane >> 2) + (sl & 1) * 8;
        const int cc = (lane & 3) + (sl >> 1) * 4;
        po[sl] = f2tf32f(x[(size_t)(mtg * 16 + ir) * DD + kkg * 8 + cc]);
    }
    *(float4*)&g_x4[(size_t)c * 128 + lane * 4] = o;
}

// Prepass: [Wqk|Wv] -> pair-packed B-frag tf32 layout.
__global__ __launch_bounds__(256) void prep_w(const float* __restrict__ Wqk,
                                              const float* __restrict__ Wv)
{
    const int g = blockIdx.x * 256 + threadIdx.x;   // 0..786431
    const int lane = g & 31, c = g >> 5;            // chunk 0..24575
    const int kkg = c & 127, ntpg = c >> 7;         // ntpg 0..191
    float4 o;
    float* po = (float*)&o;
#pragma unroll
    for (int sub = 0; sub < 4; sub++) {
        const int pnt = sub >> 1, sl = sub & 1;
        const int n = (ntpg * 2 + pnt) * 8 + (lane >> 2);
        const int k = kkg * 8 + (lane & 3) + sl * 4;
        const float* W; int ldw, col;
        if (n < NQK) { W = Wqk; ldw = NQK; col = n; }
        else         { W = Wv;  ldw = DD;  col = n - NQK; }
        po[sub] = f2tf32f(W[(size_t)k * ldw + col]);
    }
    *(float4*)&g_w[(size_t)c * 128 + lane * 4] = o;
}

// ---------------------------------------------------------------------------
// QKV GEMM: 128x128 block tile, k-step 32, 3-stage cp.async pipeline.
// 8 warps (2x4), 64x32 warp tiles, pair-packed B (LDS.128 -> 2 mma).
// ---------------------------------------------------------------------------
__global__ __launch_bounds__(256, 2) void qkv_gemm(const float* __restrict__ bqk,
                                                   const float* __restrict__ bv)
{
    extern __shared__ float sm[];
    const uint32_t sb = (uint32_t)__cvta_generic_to_shared(sm);
    // stage s: A at sm + s*8192 (4096 floats), B at +4096. 3 stages, 96KB.

    const int bm = blockIdx.y, bn = blockIdx.x;
    const int n0 = bn * 128;
    const int tid = threadIdx.x, warp = tid >> 5, lane = tid & 31;
    const int wm = warp >> 2, wn = warp & 3;      // 2 x 4 warp grid, 64x32 each
    const int gid = lane >> 2, tig = lane & 3;

    float c[4][4][4];
#pragma unroll
    for (int i = 0; i < 4; i++)
#pragma unroll
        for (int j = 0; j < 4; j++)
#pragma unroll
            for (int s = 0; s < 4; s++) c[i][j][s] = 0.f;

    auto load_stage = [&](int it, int s) {
        const int kkg0 = it * 4;
        const uint32_t S = sb + s * 32768;
#pragma unroll
        for (int i = 0; i < 4; i++) {       // A: 32 chunks x 512B
            const int id = tid + i * 256;
            const int chunk = id >> 5, off = id & 31;
            const int kk = chunk >> 3, mt = chunk & 7;
            const float* src = &g_x4[((size_t)(bm * 8 + mt) * 128 + kkg0 + kk) * 128 + off * 4];
            cp16(S + (chunk * 128 + off * 4) * 4, src);
        }
#pragma unroll
        for (int i = 0; i < 4; i++) {       // B: 32 chunks x 512B (paired)
            const int id = tid + i * 256;
            const int chunk = id >> 5, off = id & 31;
            const int kk = chunk >> 3, ntp = chunk & 7;
            const float* src = &g_w[((size_t)(bn * 8 + ntp) * 128 + kkg0 + kk) * 128 + off * 4];
            cp16(S + 16384 + (chunk * 128 + off * 4) * 4, src);
        }
    };

    load_stage(0, 0); CP_COMMIT();
    load_stage(1, 1); CP_COMMIT();

    for (int it = 0; it < 32; it++) {
        const int s = it - (it / 3) * 3;     // it % 3
        asm volatile("cp.async.wait_group 1;" ::: "memory");   // stage it arrived
        __syncthreads();                     // all warps done with stage it-1 too
        if (it + 2 < 32) {                   // prefetch into recycled slot
            int s2 = it + 2; s2 = s2 - (s2 / 3) * 3;
            load_stage(it + 2, s2);
            CP_COMMIT();
        }

        const float* As = sm + s * 8192;
        const float* Bs = sm + s * 8192 + 4096;
#pragma unroll
        for (int kk = 0; kk < 4; kk++) {
            uint32_t af[4][4], bf[4][2];
#pragma unroll
            for (int mt = 0; mt < 4; mt++) {
                float4 t = *(const float4*)&As[(((kk << 3) + (wm * 4 + mt)) * 32 + lane) * 4];
                af[mt][0] = __float_as_uint(t.x); af[mt][1] = __float_as_uint(t.y);
                af[mt][2] = __float_as_uint(t.z); af[mt][3] = __float_as_uint(t.w);
            }
#pragma unroll
            for (int ntpi = 0; ntpi < 2; ntpi++) {   // paired: 2 LDS.128 -> 4 frags
                float4 t = *(const float4*)&Bs[(((kk << 3) + (wn * 2 + ntpi)) * 32 + lane) * 4];
                bf[2 * ntpi][0]     = __float_as_uint(t.x);
                bf[2 * ntpi][1]     = __float_as_uint(t.y);
                bf[2 * ntpi + 1][0] = __float_as_uint(t.z);
                bf[2 * ntpi + 1][1] = __float_as_uint(t.w);
            }
#pragma unroll
            for (int mt = 0; mt < 4; mt++)
#pragma unroll
                for (int nt = 0; nt < 4; nt++)
                    mma_tf32(c[mt][nt], af[mt][0], af[mt][1], af[mt][2], af[mt][3],
                             bf[nt][0], bf[nt][1]);
        }
    }

    // Epilogue: bias, q-scale, tf32-round, scatter to fragment-permuted q/k/v
    const int typ = (n0 < DD) ? 0 : (n0 < NQK ? 1 : 2);
    const float* bias = (typ == 2) ? bv : bqk;
    const int bcol0 = (typ == 2) ? (n0 - NQK) : n0;
    const int nnbase = (typ == 0) ? n0 : (typ == 1 ? n0 - DD : n0 - NQK);

#pragma unroll
    for (int nt = 0; nt < 4; nt++) {
        const int ncl = wn * 32 + nt * 8 + tig * 2;
        const float b0 = bias[bcol0 + ncl];
        const float b1 = bias[bcol0 + ncl + 1];
        const int nn = nnbase + ncl;
        const int h = nn >> 6;
        const int d0 = nn & 63;      // even
#pragma unroll
        for (int mt = 0; mt < 4; mt++) {
#pragma unroll
            for (int half = 0; half < 2; half++) {
                const int m = bm * 128 + wm * 64 + mt * 16 + gid + half * 8;
                const int bb = m >> 11, s = m & (SS - 1);
                const int head = bb * HH + h;
                float v0 = c[mt][nt][half * 2 + 0] + b0;
                float v1 = c[mt][nt][half * 2 + 1] + b1;
                if (typ == 0) {
                    v0 *= 0.125f; v1 *= 0.125f;
                    const int rg = s >> 4, ir = s & 15;
                    const int kk = d0 >> 3;
                    const int cc0 = d0 & 7, cc1 = cc0 + 1;
                    const int lnb = (ir & 7) * 4;
                    const int slb = ir >> 3;
                    const size_t base = (((size_t)head * 128 + rg) * 8 + kk) * 128;
                    g_qp[base + (lnb + (cc0 & 3)) * 4 + slb + ((cc0 >> 2) << 1)] = f2tf32f(v0);
                    g_qp[base + (lnb + (cc1 & 3)) * 4 + slb + ((cc1 >> 2) << 1)] = f2tf32f(v1);
                } else if (typ == 1) {
                    const int tile = s >> 6, j = s & 63;
                    const int ntp = j >> 4, pnt = (j >> 3) & 1, nc = j & 7;
                    const int kk = d0 >> 3;
                    const int kr0 = d0 & 7, kr1 = kr0 + 1;   // kr0 even
                    const size_t base = ((((size_t)head * 32 + tile) * 8 + kk) * 4 + ntp) * 128;
                    g_kp[base + (nc * 4 + (kr0 & 3)) * 4 + pnt * 2 + (kr0 >> 2)] = f2tf32f(v0);
                    g_kp[base + (nc * 4 + (kr1 & 3)) * 4 + pnt * 2 + (kr1 >> 2)] = f2tf32f(v1);
                } else {
                    const int tile = s >> 6, j = s & 63;
                    const int kk2 = j >> 3, kr = j & 7;
                    const int ntp2 = d0 >> 4, pnt2 = (d0 >> 3) & 1;
                    const int nc0 = d0 & 7, nc1 = nc0 + 1;
                    const int sub = pnt2 * 2 + (kr >> 2);
                    const size_t base = ((((size_t)head * 32 + tile) * 8 + kk2) * 4 + ntp2) * 128;
                    g_vp[base + (nc0 * 4 + (kr & 3)) * 4 + sub] = f2tf32f(v0);
                    g_vp[base + (nc1 * 4 + (kr & 3)) * 4 + sub] = f2tf32f(v1);
                }
            }
        }
    }
}

// ---------------------------------------------------------------------------
// Causal flash attention (R10, best known): 128 q rows/block, 4 warps x 32
// rows, pair-packed K/V frags, bulk cp.async double buffering, shfl P-transpose.
// ---------------------------------------------------------------------------
__global__ __launch_bounds__(128, 2) void attn_kernel(float* __restrict__ out)
{
    extern __shared__ float sm[];
    const uint32_t sb = (uint32_t)__cvta_generic_to_shared(sm);

    const int head = blockIdx.x;
    const int qt = (gridDim.y - 1) - blockIdx.y;   // heavy first, chip-wide
    const int b = head >> 4, h = head & 15;
    const int tid = threadIdx.x, warp = tid >> 5, lane = tid & 31;
    const int gid = lane >> 2, tig = lane & 3;
    const int q0 = qt * 128;

    uint32_t qa[2][8][4];
#pragma unroll
    for (int mt = 0; mt < 2; mt++) {
        const float* qsrc = g_qp + ((size_t)head * 128 + qt * 8 + warp * 2 + mt) * 1024;
#pragma unroll
        for (int kk = 0; kk < 8; kk++) {
            float4 t = *(const float4*)&qsrc[kk * 128 + lane * 4];
            qa[mt][kk][0] = __float_as_uint(t.x); qa[mt][kk][1] = __float_as_uint(t.y);
            qa[mt][kk][2] = __float_as_uint(t.z); qa[mt][kk][3] = __float_as_uint(t.w);
        }
    }

    float O[2][8][4];
#pragma unroll
    for (int mt = 0; mt < 2; mt++)
#pragma unroll
        for (int n = 0; n < 8; n++)
#pragma unroll
            for (int s = 0; s < 4; s++) O[mt][n][s] = 0.f;
    float m_[2][2], l_[2][2];
#pragma unroll
    for (int mt = 0; mt < 2; mt++) { m_[mt][0] = m_[mt][1] = -1e30f; l_[mt][0] = l_[mt][1] = 0.f; }

    const int KTILES = 2 * qt + 2;
    const float* kbase = g_kp + (size_t)head * 131072;
    const float* vbase = g_vp + (size_t)head * 131072;

#pragma unroll
    for (int i = 0; i < 8; i++) {
        const int id = tid + i * 128;
        cp16(sb + id * 16, kbase + id * 4);
        cp16(sb + 16384 + id * 16, vbase + id * 4);
    }
    CP_COMMIT();

    for (int kt = 0; kt < KTILES; kt++) {
        const int buf = kt & 1;
        asm volatile("cp.async.wait_group 0;" ::: "memory");
        __syncthreads();
        if (kt + 1 < KTILES) {
            const float* ks = kbase + (size_t)(kt + 1) * 4096;
            const float* vs = vbase + (size_t)(kt + 1) * 4096;
            const uint32_t db = sb + (1 - buf) * 32768;
#pragma unroll
            for (int i = 0; i < 8; i++) {
                const int id = tid + i * 128;
                cp16(db + id * 16, ks + id * 4);
                cp16(db + 16384 + id * 16, vs + id * 4);
            }
            CP_COMMIT();
        }

        const float* Ks = sm + buf * 8192;
        const float* Vs = sm + buf * 8192 + 4096;
        const int k0 = kt * 64;

        float S[2][8][4];
#pragma unroll
        for (int mt = 0; mt < 2; mt++)
#pragma unroll
            for (int n = 0; n < 8; n++)
#pragma unroll
                for (int s = 0; s < 4; s++) S[mt][n][s] = 0.f;
#pragma unroll
        for (int kk = 0; kk < 8; kk++) {
#pragma unroll
            for (int ntp = 0; ntp < 4; ntp++) {
                float4 t = *(const float4*)&Ks[((kk * 4 + ntp) * 32 + lane) * 4];
                const uint32_t b0 = __float_as_uint(t.x), b1 = __float_as_uint(t.y);
                const uint32_t b2 = __float_as_uint(t.z), b3 = __float_as_uint(t.w);
#pragma unroll
                for (int mt = 0; mt < 2; mt++) {
                    mma_tf32(S[mt][2 * ntp], qa[mt][kk][0], qa[mt][kk][1],
                             qa[mt][kk][2], qa[mt][kk][3], b0, b1);
                    mma_tf32(S[mt][2 * ntp + 1], qa[mt][kk][0], qa[mt][kk][1],
                             qa[mt][kk][2], qa[mt][kk][3], b2, b3);
                }
            }
        }

#pragma unroll
        for (int mt = 0; mt < 2; mt++) {
            const int rbase = q0 + warp * 32 + mt * 16;
            if (k0 + 63 > rbase) {
#pragma unroll
                for (int nt = 0; nt < 8; nt++)
#pragma unroll
                    for (int sl = 0; sl < 4; sl++) {
                        const int key = k0 + nt * 8 + tig * 2 + (sl & 1);
                        const int row = rbase + gid + (sl >> 1) * 8;
                        if (key > row) S[mt][nt][sl] = -1e30f;
                    }
            }

            float mx_a = -1e30f, mx_b = -1e30f;
#pragma unroll
            for (int nt = 0; nt < 8; nt++) {
                mx_a = fmaxf(mx_a, fmaxf(S[mt][nt][0], S[mt][nt][1]));
                mx_b = fmaxf(mx_b, fmaxf(S[mt][nt][2], S[mt][nt][3]));
            }
            mx_a = fmaxf(mx_a, __shfl_xor_sync(0xffffffffu, mx_a, 1));
            mx_a = fmaxf(mx_a, __shfl_xor_sync(0xffffffffu, mx_a, 2));
            mx_b = fmaxf(mx_b, __shfl_xor_sync(0xffffffffu, mx_b, 1));
            mx_b = fmaxf(mx_b, __shfl_xor_sync(0xffffffffu, mx_b, 2));

            const float na = fmaxf(m_[mt][0], mx_a), nb = fmaxf(m_[mt][1], mx_b);
            const float ca = __expf(m_[mt][0] - na), cb = __expf(m_[mt][1] - nb);
            m_[mt][0] = na; m_[mt][1] = nb;

            float sa = 0.f, sbv = 0.f;
#pragma unroll
            for (int nt = 0; nt < 8; nt++) {
#pragma unroll
                for (int sl = 0; sl < 4; sl++) {
                    const float p = __expf(S[mt][nt][sl] - ((sl < 2) ? na : nb));
                    const float ptf = f2tf32f(p);      // round before summing
                    if (sl < 2) sa += ptf; else sbv += ptf;
                    S[mt][nt][sl] = ptf;               // S now holds P (tf32)
                }
            }
            sa  += __shfl_xor_sync(0xffffffffu, sa, 1);
            sa  += __shfl_xor_sync(0xffffffffu, sa, 2);
            sbv += __shfl_xor_sync(0xffffffffu, sbv, 1);
            sbv += __shfl_xor_sync(0xffffffffu, sbv, 2);
            l_[mt][0] = l_[mt][0] * ca + sa;
            l_[mt][1] = l_[mt][1] * cb + sbv;
#pragma unroll
            for (int n = 0; n < 8; n++) {
                O[mt][n][0] *= ca; O[mt][n][1] *= ca;
                O[mt][n][2] *= cb; O[mt][n][3] *= cb;
            }
        }

        const int l0 = gid * 4 + (tig >> 1);
        const int l2 = l0 + 2;
        const bool odd = (tig & 1);
#pragma unroll
        for (int kk2 = 0; kk2 < 8; kk2++) {
            float4 v[4];
#pragma unroll
            for (int ntp2 = 0; ntp2 < 4; ntp2++)
                v[ntp2] = *(const float4*)&Vs[((kk2 * 4 + ntp2) * 32 + lane) * 4];
#pragma unroll
            for (int mt = 0; mt < 2; mt++) {
                const float e00 = __shfl_sync(0xffffffffu, S[mt][kk2][0], l0);
                const float e01 = __shfl_sync(0xffffffffu, S[mt][kk2][1], l0);
                const float e10 = __shfl_sync(0xffffffffu, S[mt][kk2][2], l0);
                const float e11 = __shfl_sync(0xffffffffu, S[mt][kk2][3], l0);
                const float e20 = __shfl_sync(0xffffffffu, S[mt][kk2][0], l2);
                const float e21 = __shfl_sync(0xffffffffu, S[mt][kk2][1], l2);
                const float e30 = __shfl_sync(0xffffffffu, S[mt][kk2][2], l2);
                const float e31 = __shfl_sync(0xffffffffu, S[mt][kk2][3], l2);
                const uint32_t a0 = __float_as_uint(odd ? e01 : e00);
                const uint32_t a1 = __float_as_uint(odd ? e11 : e10);
                const uint32_t a2 = __float_as_uint(odd ? e21 : e20);
                const uint32_t a3 = __float_as_uint(odd ? e31 : e30);
#pragma unroll
                for (int ntp2 = 0; ntp2 < 4; ntp2++) {
                    mma_tf32(O[mt][2 * ntp2], a0, a1, a2, a3,
                             __float_as_uint(v[ntp2].x), __float_as_uint(v[ntp2].y));
                    mma_tf32(O[mt][2 * ntp2 + 1], a0, a1, a2, a3,
                             __float_as_uint(v[ntp2].z), __float_as_uint(v[ntp2].w));
                }
            }
        }
    }

#pragma unroll
    for (int mt = 0; mt < 2; mt++) {
        const float inva = 1.f / l_[mt][0], invb = 1.f / l_[mt][1];
        const int ra = q0 + warp * 32 + mt * 16 + gid;
        const int rb = ra + 8;
        float* oa = out + ((size_t)(b * SS + ra)) * DD + (size_t)h * 64;
        float* ob = out + ((size_t)(b * SS + rb)) * DD + (size_t)h * 64;
#pragma unroll
        for (int nt2 = 0; nt2 < 8; nt2++) {
            const int col = nt2 * 8 + tig * 2;
            float2 va, vb2;
            va.x  = O[mt][nt2][0] * inva; va.y  = O[mt][nt2][1] * inva;
            vb2.x = O[mt][nt2][2] * invb; vb2.y = O[mt][nt2][3] * invb;
            *(float2*)&oa[col] = va;
            *(float2*)&ob[col] = vb2;
        }
    }
}

// ---------------------------------------------------------------------------
extern "C" void kernel_launch(void* const* d_in, const int* in_sizes, int n_in,
                              void* d_out, int out_size)
{
    const float* x   = (const float*)d_in[0];
    const float* Wqk = (const float*)d_in[1];
    const float* bqk = (const float*)d_in[2];
    const float* Wv  = (const float*)d_in[3];
    const float* bv  = (const float*)d_in[4];
    float* out = (float*)d_out;

    prep_x<<<4096, 256>>>(x);
    prep_w<<<3072, 256>>>(Wqk, Wv);

    cudaFuncSetAttribute(qkv_gemm, cudaFuncAttributeMaxDynamicSharedMemorySize, 98304);
    qkv_gemm<<<dim3(24, 32), 256, 98304>>>(bqk, bv);

    cudaFuncSetAttribute(attn_kernel, cudaFuncAttributeMaxDynamicSharedMemorySize, 65536);
    attn_kernel<<<dim3(32, 16), 128, 65536>>>(out);
}

// round 17
// speedup vs baseline: 1.5361x; 1.5361x over previous
#include <cuda_runtime.h>
#include <cstdint>

#define BB 2
#define SS 2048
#define DD 1024
#define HH 16
#define NQK 2048
#define NTOT 3072

// tf32 fragment-permuted scratch (all values pre-rounded to tf32):
// g_x4 : x as A-frags        [mtg(256)][kkg(128)][lane(32)][slot(4)]
// g_w  : W as PAIRED B-frags [ntpg(192)][kkg(128)][lane(32)][4]
// g_qp : q as A-frags        [head(32)][rg(128)][kk(8)][lane(32)][slot(4)] (q pre-scaled 1/8)
// g_kp : k as PAIRED B-frags [head(32)][tile(32)][kk(8)][ntp(4)][lane(32)][4]
// g_vp : v as PAIRED B-frags [head(32)][tile(32)][kk2(8)][ntp2(4)][lane(32)][4]
__device__ float g_x4[4194304];
__device__ float g_w [3145728];
__device__ float g_qp[4194304];
__device__ float g_kp[4194304];
__device__ float g_vp[4194304];

// ---------------------------------------------------------------------------
__device__ __forceinline__ uint32_t f2tf32(float x) {
    uint32_t r; asm("cvt.rna.tf32.f32 %0, %1;" : "=r"(r) : "f"(x)); return r;
}
__device__ __forceinline__ float f2tf32f(float x) { return __uint_as_float(f2tf32(x)); }

__device__ __forceinline__ void mma_tf32(float c[4],
                                         uint32_t a0, uint32_t a1, uint32_t a2, uint32_t a3,
                                         uint32_t b0, uint32_t b1) {
    asm volatile(
        "mma.sync.aligned.m16n8k8.row.col.f32.tf32.tf32.f32 "
        "{%0,%1,%2,%3}, {%4,%5,%6,%7}, {%8,%9}, {%0,%1,%2,%3};"
        : "+f"(c[0]), "+f"(c[1]), "+f"(c[2]), "+f"(c[3])
        : "r"(a0), "r"(a1), "r"(a2), "r"(a3), "r"(b0), "r"(b1));
}

__device__ __forceinline__ void cp16(uint32_t dst, const void* src) {
    asm volatile("cp.async.cg.shared.global [%0], [%1], 16;" :: "r"(dst), "l"(src));
}
#define CP_COMMIT() asm volatile("cp.async.commit_group;" ::: "memory")
#define CP_WAIT0()  asm volatile("cp.async.wait_group 0;" ::: "memory")

// ---------------------------------------------------------------------------
// Merged prepass: blocks [0,4096) do x -> A-frags; [4096,7168) do W -> paired
// B-frags. One launch instead of two.
// ---------------------------------------------------------------------------
__global__ __launch_bounds__(256) void prep_xw(const float* __restrict__ x,
                                               const float* __restrict__ Wqk,
                                               const float* __restrict__ Wv)
{
    if (blockIdx.x < 4096) {
        const int g = blockIdx.x * 256 + threadIdx.x;
        const int lane = g & 31, c = g >> 5;            // chunk 0..32767
        const int kkg = c & 127, mtg = c >> 7;
        float4 o;
        float* po = (float*)&o;
#pragma unroll
        for (int sl = 0; sl < 4; sl++) {
            const int ir = (lane >> 2) + (sl & 1) * 8;
            const int cc = (lane & 3) + (sl >> 1) * 4;
            po[sl] = f2tf32f(x[(size_t)(mtg * 16 + ir) * DD + kkg * 8 + cc]);
        }
        *(float4*)&g_x4[(size_t)c * 128 + lane * 4] = o;
    } else {
        const int g = (blockIdx.x - 4096) * 256 + threadIdx.x;   // 0..786431
        const int lane = g & 31, c = g >> 5;            // chunk 0..24575
        const int kkg = c & 127, ntpg = c >> 7;         // ntpg 0..191
        float4 o;
        float* po = (float*)&o;
#pragma unroll
        for (int sub = 0; sub < 4; sub++) {
            const int pnt = sub >> 1, sl = sub & 1;
            const int n = (ntpg * 2 + pnt) * 8 + (lane >> 2);
            const int k = kkg * 8 + (lane & 3) + sl * 4;
            const float* W; int ldw, col;
            if (n < NQK) { W = Wqk; ldw = NQK; col = n; }
            else         { W = Wv;  ldw = DD;  col = n - NQK; }
            po[sub] = f2tf32f(W[(size_t)k * ldw + col]);
        }
        *(float4*)&g_w[(size_t)c * 128 + lane * 4] = o;
    }
}

// ---------------------------------------------------------------------------
// QKV GEMM (R9 measured-best config): 128x128 block tile, k-step 32, cp.async
// double-buffered, 8 warps (2x4), 64x32 warp tiles, pair-packed B.
// ---------------------------------------------------------------------------
__global__ __launch_bounds__(256, 2) void qkv_gemm(const float* __restrict__ bqk,
                                                   const float* __restrict__ bv)
{
    extern __shared__ float sm[];
    const uint32_t sb = (uint32_t)__cvta_generic_to_shared(sm);
    // As(buf) = sm + buf*4096; Bs(buf) = sm + 8192 + buf*4096 (floats).

    const int bm = blockIdx.y, bn = blockIdx.x;
    const int n0 = bn * 128;
    const int tid = threadIdx.x, warp = tid >> 5, lane = tid & 31;
    const int wm = warp >> 2, wn = warp & 3;      // 2 x 4 warp grid, 64x32 each
    const int gid = lane >> 2, tig = lane & 3;

    float c[4][4][4];
#pragma unroll
    for (int i = 0; i < 4; i++)
#pragma unroll
        for (int j = 0; j < 4; j++)
#pragma unroll
            for (int s = 0; s < 4; s++) c[i][j][s] = 0.f;

    auto load_tile = [&](int it, int buf) {
        const int kkg0 = it * 4;
#pragma unroll
        for (int i = 0; i < 4; i++) {       // A: 32 chunks x 512B
            const int id = tid + i * 256;
            const int chunk = id >> 5, off = id & 31;
            const int kk = chunk >> 3, mt = chunk & 7;
            const float* src = &g_x4[((size_t)(bm * 8 + mt) * 128 + kkg0 + kk) * 128 + off * 4];
            cp16(sb + (buf * 4096 + chunk * 128 + off * 4) * 4, src);
        }
#pragma unroll
        for (int i = 0; i < 4; i++) {       // B: 32 chunks x 512B (paired)
            const int id = tid + i * 256;
            const int chunk = id >> 5, off = id & 31;
            const int kk = chunk >> 3, ntp = chunk & 7;
            const float* src = &g_w[((size_t)(bn * 8 + ntp) * 128 + kkg0 + kk) * 128 + off * 4];
            cp16(sb + (8192 + buf * 4096 + chunk * 128 + off * 4) * 4, src);
        }
    };

    load_tile(0, 0);
    CP_COMMIT();

    for (int it = 0; it < 32; it++) {
        const int buf = it & 1;
        CP_WAIT0();
        __syncthreads();
        if (it + 1 < 32) { load_tile(it + 1, 1 - buf); CP_COMMIT(); }

        const float* As = sm + buf * 4096;
        const float* Bs = sm + 8192 + buf * 4096;
#pragma unroll
        for (int kk = 0; kk < 4; kk++) {
            uint32_t af[4][4], bf[4][2];
#pragma unroll
            for (int mt = 0; mt < 4; mt++) {
                float4 t = *(const float4*)&As[(((kk << 3) + (wm * 4 + mt)) * 32 + lane) * 4];
                af[mt][0] = __float_as_uint(t.x); af[mt][1] = __float_as_uint(t.y);
                af[mt][2] = __float_as_uint(t.z); af[mt][3] = __float_as_uint(t.w);
            }
#pragma unroll
            for (int ntpi = 0; ntpi < 2; ntpi++) {   // paired: 2 LDS.128 -> 4 frags
                float4 t = *(const float4*)&Bs[(((kk << 3) + (wn * 2 + ntpi)) * 32 + lane) * 4];
                bf[2 * ntpi][0]     = __float_as_uint(t.x);
                bf[2 * ntpi][1]     = __float_as_uint(t.y);
                bf[2 * ntpi + 1][0] = __float_as_uint(t.z);
                bf[2 * ntpi + 1][1] = __float_as_uint(t.w);
            }
#pragma unroll
            for (int mt = 0; mt < 4; mt++)
#pragma unroll
                for (int nt = 0; nt < 4; nt++)
                    mma_tf32(c[mt][nt], af[mt][0], af[mt][1], af[mt][2], af[mt][3],
                             bf[nt][0], bf[nt][1]);
        }
    }

    // Epilogue: bias, q-scale, tf32-round, scatter to fragment-permuted q/k/v
    const int typ = (n0 < DD) ? 0 : (n0 < NQK ? 1 : 2);
    const float* bias = (typ == 2) ? bv : bqk;
    const int bcol0 = (typ == 2) ? (n0 - NQK) : n0;
    const int nnbase = (typ == 0) ? n0 : (typ == 1 ? n0 - DD : n0 - NQK);

#pragma unroll
    for (int nt = 0; nt < 4; nt++) {
        const int ncl = wn * 32 + nt * 8 + tig * 2;
        const float b0 = bias[bcol0 + ncl];
        const float b1 = bias[bcol0 + ncl + 1];
        const int nn = nnbase + ncl;
        const int h = nn >> 6;
        const int d0 = nn & 63;      // even
#pragma unroll
        for (int mt = 0; mt < 4; mt++) {
#pragma unroll
            for (int half = 0; half < 2; half++) {
                const int m = bm * 128 + wm * 64 + mt * 16 + gid + half * 8;
                const int bb = m >> 11, s = m & (SS - 1);
                const int head = bb * HH + h;
                float v0 = c[mt][nt][half * 2 + 0] + b0;
                float v1 = c[mt][nt][half * 2 + 1] + b1;
                if (typ == 0) {
                    v0 *= 0.125f; v1 *= 0.125f;
                    const int rg = s >> 4, ir = s & 15;
                    const int kk = d0 >> 3;
                    const int cc0 = d0 & 7, cc1 = cc0 + 1;
                    const int lnb = (ir & 7) * 4;
                    const int slb = ir >> 3;
                    const size_t base = (((size_t)head * 128 + rg) * 8 + kk) * 128;
                    g_qp[base + (lnb + (cc0 & 3)) * 4 + slb + ((cc0 >> 2) << 1)] = f2tf32f(v0);
                    g_qp[base + (lnb + (cc1 & 3)) * 4 + slb + ((cc1 >> 2) << 1)] = f2tf32f(v1);
                } else if (typ == 1) {
                    const int tile = s >> 6, j = s & 63;
                    const int ntp = j >> 4, pnt = (j >> 3) & 1, nc = j & 7;
                    const int kk = d0 >> 3;
                    const int kr0 = d0 & 7, kr1 = kr0 + 1;   // kr0 even
                    const size_t base = ((((size_t)head * 32 + tile) * 8 + kk) * 4 + ntp) * 128;
                    g_kp[base + (nc * 4 + (kr0 & 3)) * 4 + pnt * 2 + (kr0 >> 2)] = f2tf32f(v0);
                    g_kp[base + (nc * 4 + (kr1 & 3)) * 4 + pnt * 2 + (kr1 >> 2)] = f2tf32f(v1);
                } else {
                    const int tile = s >> 6, j = s & 63;
                    const int kk2 = j >> 3, kr = j & 7;
                    const int ntp2 = d0 >> 4, pnt2 = (d0 >> 3) & 1;
                    const int nc0 = d0 & 7, nc1 = nc0 + 1;
                    const int sub = pnt2 * 2 + (kr >> 2);
                    const size_t base = ((((size_t)head * 32 + tile) * 8 + kk2) * 4 + ntp2) * 128;
                    g_vp[base + (nc0 * 4 + (kr & 3)) * 4 + sub] = f2tf32f(v0);
                    g_vp[base + (nc1 * 4 + (kr & 3)) * 4 + sub] = f2tf32f(v1);
                }
            }
        }
    }
}

// ---------------------------------------------------------------------------
// Causal flash attention (R10, measured best = 108.6us): 128 q rows/block,
// 4 warps x 32 rows, pair-packed K/V frags, bulk cp.async double buffering,
// shfl P-transpose.
// ---------------------------------------------------------------------------
__global__ __launch_bounds__(128, 2) void attn_kernel(float* __restrict__ out)
{
    extern __shared__ float sm[];
    const uint32_t sb = (uint32_t)__cvta_generic_to_shared(sm);

    const int head = blockIdx.x;
    const int qt = (gridDim.y - 1) - blockIdx.y;   // heavy first, chip-wide
    const int b = head >> 4, h = head & 15;
    const int tid = threadIdx.x, warp = tid >> 5, lane = tid & 31;
    const int gid = lane >> 2, tig = lane & 3;
    const int q0 = qt * 128;

    uint32_t qa[2][8][4];
#pragma unroll
    for (int mt = 0; mt < 2; mt++) {
        const float* qsrc = g_qp + ((size_t)head * 128 + qt * 8 + warp * 2 + mt) * 1024;
#pragma unroll
        for (int kk = 0; kk < 8; kk++) {
            float4 t = *(const float4*)&qsrc[kk * 128 + lane * 4];
            qa[mt][kk][0] = __float_as_uint(t.x); qa[mt][kk][1] = __float_as_uint(t.y);
            qa[mt][kk][2] = __float_as_uint(t.z); qa[mt][kk][3] = __float_as_uint(t.w);
        }
    }

    float O[2][8][4];
#pragma unroll
    for (int mt = 0; mt < 2; mt++)
#pragma unroll
        for (int n = 0; n < 8; n++)
#pragma unroll
            for (int s = 0; s < 4; s++) O[mt][n][s] = 0.f;
    float m_[2][2], l_[2][2];
#pragma unroll
    for (int mt = 0; mt < 2; mt++) { m_[mt][0] = m_[mt][1] = -1e30f; l_[mt][0] = l_[mt][1] = 0.f; }

    const int KTILES = 2 * qt + 2;
    const float* kbase = g_kp + (size_t)head * 131072;
    const float* vbase = g_vp + (size_t)head * 131072;

#pragma unroll
    for (int i = 0; i < 8; i++) {
        const int id = tid + i * 128;
        cp16(sb + id * 16, kbase + id * 4);
        cp16(sb + 16384 + id * 16, vbase + id * 4);
    }
    CP_COMMIT();

    for (int kt = 0; kt < KTILES; kt++) {
        const int buf = kt & 1;
        CP_WAIT0();
        __syncthreads();
        if (kt + 1 < KTILES) {
            const float* ks = kbase + (size_t)(kt + 1) * 4096;
            const float* vs = vbase + (size_t)(kt + 1) * 4096;
            const uint32_t db = sb + (1 - buf) * 32768;
#pragma unroll
            for (int i = 0; i < 8; i++) {
                const int id = tid + i * 128;
                cp16(db + id * 16, ks + id * 4);
                cp16(db + 16384 + id * 16, vs + id * 4);
            }
            CP_COMMIT();
        }

        const float* Ks = sm + buf * 8192;
        const float* Vs = sm + buf * 8192 + 4096;
        const int k0 = kt * 64;

        float S[2][8][4];
#pragma unroll
        for (int mt = 0; mt < 2; mt++)
#pragma unroll
            for (int n = 0; n < 8; n++)
#pragma unroll
                for (int s = 0; s < 4; s++) S[mt][n][s] = 0.f;
#pragma unroll
        for (int kk = 0; kk < 8; kk++) {
#pragma unroll
            for (int ntp = 0; ntp < 4; ntp++) {
                float4 t = *(const float4*)&Ks[((kk * 4 + ntp) * 32 + lane) * 4];
                const uint32_t b0 = __float_as_uint(t.x), b1 = __float_as_uint(t.y);
                const uint32_t b2 = __float_as_uint(t.z), b3 = __float_as_uint(t.w);
#pragma unroll
                for (int mt = 0; mt < 2; mt++) {
                    mma_tf32(S[mt][2 * ntp], qa[mt][kk][0], qa[mt][kk][1],
                             qa[mt][kk][2], qa[mt][kk][3], b0, b1);
                    mma_tf32(S[mt][2 * ntp + 1], qa[mt][kk][0], qa[mt][kk][1],
                             qa[mt][kk][2], qa[mt][kk][3], b2, b3);
                }
            }
        }

#pragma unroll
        for (int mt = 0; mt < 2; mt++) {
            const int rbase = q0 + warp * 32 + mt * 16;
            if (k0 + 63 > rbase) {
#pragma unroll
                for (int nt = 0; nt < 8; nt++)
#pragma unroll
                    for (int sl = 0; sl < 4; sl++) {
                        const int key = k0 + nt * 8 + tig * 2 + (sl & 1);
                        const int row = rbase + gid + (sl >> 1) * 8;
                        if (key > row) S[mt][nt][sl] = -1e30f;
                    }
            }

            float mx_a = -1e30f, mx_b = -1e30f;
#pragma unroll
            for (int nt = 0; nt < 8; nt++) {
                mx_a = fmaxf(mx_a, fmaxf(S[mt][nt][0], S[mt][nt][1]));
                mx_b = fmaxf(mx_b, fmaxf(S[mt][nt][2], S[mt][nt][3]));
            }
            mx_a = fmaxf(mx_a, __shfl_xor_sync(0xffffffffu, mx_a, 1));
            mx_a = fmaxf(mx_a, __shfl_xor_sync(0xffffffffu, mx_a, 2));
            mx_b = fmaxf(mx_b, __shfl_xor_sync(0xffffffffu, mx_b, 1));
            mx_b = fmaxf(mx_b, __shfl_xor_sync(0xffffffffu, mx_b, 2));

            const float na = fmaxf(m_[mt][0], mx_a), nb = fmaxf(m_[mt][1], mx_b);
            const float ca = __expf(m_[mt][0] - na), cb = __expf(m_[mt][1] - nb);
            m_[mt][0] = na; m_[mt][1] = nb;

            float sa = 0.f, sbv = 0.f;
#pragma unroll
            for (int nt = 0; nt < 8; nt++) {
#pragma unroll
                for (int sl = 0; sl < 4; sl++) {
                    const float p = __expf(S[mt][nt][sl] - ((sl < 2) ? na : nb));
                    const float ptf = f2tf32f(p);      // round before summing
                    if (sl < 2) sa += ptf; else sbv += ptf;
                    S[mt][nt][sl] = ptf;               // S now holds P (tf32)
                }
            }
            sa  += __shfl_xor_sync(0xffffffffu, sa, 1);
            sa  += __shfl_xor_sync(0xffffffffu, sa, 2);
            sbv += __shfl_xor_sync(0xffffffffu, sbv, 1);
            sbv += __shfl_xor_sync(0xffffffffu, sbv, 2);
            l_[mt][0] = l_[mt][0] * ca + sa;
            l_[mt][1] = l_[mt][1] * cb + sbv;
#pragma unroll
            for (int n = 0; n < 8; n++) {
                O[mt][n][0] *= ca; O[mt][n][1] *= ca;
                O[mt][n][2] *= cb; O[mt][n][3] *= cb;
            }
        }

        const int l0 = gid * 4 + (tig >> 1);
        const int l2 = l0 + 2;
        const bool odd = (tig & 1);
#pragma unroll
        for (int kk2 = 0; kk2 < 8; kk2++) {
            float4 v[4];
#pragma unroll
            for (int ntp2 = 0; ntp2 < 4; ntp2++)
                v[ntp2] = *(const float4*)&Vs[((kk2 * 4 + ntp2) * 32 + lane) * 4];
#pragma unroll
            for (int mt = 0; mt < 2; mt++) {
                const float e00 = __shfl_sync(0xffffffffu, S[mt][kk2][0], l0);
                const float e01 = __shfl_sync(0xffffffffu, S[mt][kk2][1], l0);
                const float e10 = __shfl_sync(0xffffffffu, S[mt][kk2][2], l0);
                const float e11 = __shfl_sync(0xffffffffu, S[mt][kk2][3], l0);
                const float e20 = __shfl_sync(0xffffffffu, S[mt][kk2][0], l2);
                const float e21 = __shfl_sync(0xffffffffu, S[mt][kk2][1], l2);
                const float e30 = __shfl_sync(0xffffffffu, S[mt][kk2][2], l2);
                const float e31 = __shfl_sync(0xffffffffu, S[mt][kk2][3], l2);
                const uint32_t a0 = __float_as_uint(odd ? e01 : e00);
                const uint32_t a1 = __float_as_uint(odd ? e11 : e10);
                const uint32_t a2 = __float_as_uint(odd ? e21 : e20);
                const uint32_t a3 = __float_as_uint(odd ? e31 : e30);
#pragma unroll
                for (int ntp2 = 0; ntp2 < 4; ntp2++) {
                    mma_tf32(O[mt][2 * ntp2], a0, a1, a2, a3,
                             __float_as_uint(v[ntp2].x), __float_as_uint(v[ntp2].y));
                    mma_tf32(O[mt][2 * ntp2 + 1], a0, a1, a2, a3,
                             __float_as_uint(v[ntp2].z), __float_as_uint(v[ntp2].w));
                }
            }
        }
    }

#pragma unroll
    for (int mt = 0; mt < 2; mt++) {
        const float inva = 1.f / l_[mt][0], invb = 1.f / l_[mt][1];
        const int ra = q0 + warp * 32 + mt * 16 + gid;
        const int rb = ra + 8;
        float* oa = out + ((size_t)(b * SS + ra)) * DD + (size_t)h * 64;
        float* ob = out + ((size_t)(b * SS + rb)) * DD + (size_t)h * 64;
#pragma unroll
        for (int nt2 = 0; nt2 < 8; nt2++) {
            const int col = nt2 * 8 + tig * 2;
            float2 va, vb2;
            va.x  = O[mt][nt2][0] * inva; va.y  = O[mt][nt2][1] * inva;
            vb2.x = O[mt][nt2][2] * invb; vb2.y = O[mt][nt2][3] * invb;
            *(float2*)&oa[col] = va;
            *(float2*)&ob[col] = vb2;
        }
    }
}

// ---------------------------------------------------------------------------
extern "C" void kernel_launch(void* const* d_in, const int* in_sizes, int n_in,
                              void* d_out, int out_size)
{
    const float* x   = (const float*)d_in[0];
    const float* Wqk = (const float*)d_in[1];
    const float* bqk = (const float*)d_in[2];
    const float* Wv  = (const float*)d_in[3];
    const float* bv  = (const float*)d_in[4];
    float* out = (float*)d_out;

    prep_xw<<<7168, 256>>>(x, Wqk, Wv);

    cudaFuncSetAttribute(qkv_gemm, cudaFuncAttributeMaxDynamicSharedMemorySize, 65536);
    qkv_gemm<<<dim3(24, 32), 256, 65536>>>(bqk, bv);

    cudaFuncSetAttribute(attn_kernel, cudaFuncAttributeMaxDynamicSharedMemorySize, 65536);
    attn_kernel<<<dim3(32, 16), 128, 65536>>>(out);
}